// round 13
// baseline (speedup 1.0000x reference)
#include <cuda_runtime.h>
#include <cstdint>

#define BB 64
#define SS 512
#define HH 768
#define CC 9
#define KCH 48       // chunks per batch
#define CH  11       // steps per chunk (48*11 = 528 >= 511)
#define HWPB 8       // warps per crf half-block
#define WIN 33       // timesteps per warp window (3 chunks * 11)
#define L2E 1.4426950408889634f
#define LN2 0.6931471805599453f
#define FULLMASK 0xffffffffu

// scratch (no allocations allowed)
__device__ __align__(16) float g_emis[BB * SS * CC];   // 1.18 MB raw emissions
__device__ __align__(16) float g_P[BB * KCH * 81];     // chunk matrices
__device__ int   g_E[BB * KCH * CC];                   // per-row exponents
__device__ float g_num[BB * 16];                       // numerator partials
__device__ int   g_bar[BB];                            // per-batch arrival
__device__ float g_acc = 0.0f;
__device__ int   g_cnt = 0;

__device__ __forceinline__ float ex2f(float x) {
    float y; asm("ex2.approx.ftz.f32 %0, %1;" : "=f"(y) : "f"(x)); return y;
}
__device__ __forceinline__ float lg2f(float x) {
    float y; asm("lg2.approx.ftz.f32 %0, %1;" : "=f"(y) : "f"(x)); return y;
}

// ---------------------------------------------------------------------------
// Kernel 1: emissions = hidden @ W^T + b.
// 4 rows per warp, unroll 3 (12 LDG.128 in flight), vectorized STG.128 x9.
// ---------------------------------------------------------------------------
__global__ __launch_bounds__(256, 2) void emis_kernel(
    const float* __restrict__ hidden,
    const float* __restrict__ W,
    const float* __restrict__ bias)
{
    __shared__ alignas(16) float Wsm[CC * HH];   // 27648 B
    for (int i = threadIdx.x; i < CC * HH / 4; i += 256)
        ((float4*)Wsm)[i] = ((const float4*)W)[i];
    __syncthreads();

    float bv[CC];
#pragma unroll
    for (int c = 0; c < CC; c++) bv[c] = bias[c];

    const int lane   = threadIdx.x & 31;
    const int warp   = (blockIdx.x * blockDim.x + threadIdx.x) >> 5;
    const int nwarps = gridDim.x * (blockDim.x >> 5);
    const int NGROUPS = (BB * SS) / 4;   // 8192 groups of 4 rows

    for (int g = warp; g < NGROUPS; g += nwarps) {
        const int row0 = g * 4;
        const float4* hp0 = (const float4*)(hidden + (size_t)row0 * HH);
        const float4* hp1 = (const float4*)(hidden + (size_t)(row0 + 1) * HH);
        const float4* hp2 = (const float4*)(hidden + (size_t)(row0 + 2) * HH);
        const float4* hp3 = (const float4*)(hidden + (size_t)(row0 + 3) * HH);

        float acc[4][CC];
#pragma unroll
        for (int r = 0; r < 4; r++)
#pragma unroll
            for (int c = 0; c < CC; c++) acc[r][c] = 0.0f;

#pragma unroll 3
        for (int i = 0; i < HH / 128; i++) {   // 6 iterations
            float4 h[4];
            h[0] = hp0[i * 32 + lane];
            h[1] = hp1[i * 32 + lane];
            h[2] = hp2[i * 32 + lane];
            h[3] = hp3[i * 32 + lane];
#pragma unroll
            for (int c = 0; c < CC; c++) {
                const float4 w = ((const float4*)(Wsm + c * HH))[i * 32 + lane];
#pragma unroll
                for (int r = 0; r < 4; r++) {
                    acc[r][c] = fmaf(h[r].x, w.x, acc[r][c]);
                    acc[r][c] = fmaf(h[r].y, w.y, acc[r][c]);
                    acc[r][c] = fmaf(h[r].z, w.z, acc[r][c]);
                    acc[r][c] = fmaf(h[r].w, w.w, acc[r][c]);
                }
            }
        }
#pragma unroll
        for (int r = 0; r < 4; r++)
#pragma unroll
            for (int c = 0; c < CC; c++)
#pragma unroll
                for (int off = 16; off > 0; off >>= 1)
                    acc[r][c] += __shfl_xor_sync(FULLMASK, acc[r][c], off);

        if (lane == 0) {
            // 36 contiguous floats = 9 static float4 stores
#define AV(r, c) (acc[r][c] + bv[c])
            float4* dst = (float4*)(g_emis + (size_t)row0 * CC);
            dst[0] = make_float4(AV(0,0), AV(0,1), AV(0,2), AV(0,3));
            dst[1] = make_float4(AV(0,4), AV(0,5), AV(0,6), AV(0,7));
            dst[2] = make_float4(AV(0,8), AV(1,0), AV(1,1), AV(1,2));
            dst[3] = make_float4(AV(1,3), AV(1,4), AV(1,5), AV(1,6));
            dst[4] = make_float4(AV(1,7), AV(1,8), AV(2,0), AV(2,1));
            dst[5] = make_float4(AV(2,2), AV(2,3), AV(2,4), AV(2,5));
            dst[6] = make_float4(AV(2,6), AV(2,7), AV(2,8), AV(3,0));
            dst[7] = make_float4(AV(3,1), AV(3,2), AV(3,3), AV(3,4));
            dst[8] = make_float4(AV(3,5), AV(3,6), AV(3,7), AV(3,8));
#undef AV
        }
    }
}

// ---------------------------------------------------------------------------
// Kernel 2: CRF, 128 blocks x 256 threads. Block (2b + h) computes chunks
// [24h, 24h+24) of batch b (8 warps x 3 chunks of 11 steps), writes P/E/num
// to gmem. The SECOND block to finish for a batch stages all 48 chunks into
// smem and runs the combine + llh + atomic mean. No spin waits.
// ---------------------------------------------------------------------------
__global__ __launch_bounds__(256) void crf_kernel(
    const float* __restrict__ stv,
    const float* __restrict__ trv,
    const float* __restrict__ etv,
    const int*   __restrict__ tags,
    const int*   __restrict__ mask,
    float* __restrict__ out)
{
    __shared__ alignas(16) float eml_sm[HWPB][WIN * 12];  // 12672 B
    __shared__ alignas(16) float Psm[KCH * 81];           // 15552 B
    __shared__ alignas(16) float Te_sm[CC][12];           // exp(tr) rows
    __shared__ int   Esm[KCH * CC];                       // 1728 B
    __shared__ float tr_sh[81];
    __shared__ int   Emax_sm[KCH];
    __shared__ int   iam_last;

    const int b    = blockIdx.x >> 1;
    const int half = blockIdx.x & 1;
    const int tid  = threadIdx.x;
    const int wid  = tid >> 5;
    const int lane = tid & 31;
    const int wb   = half * HWPB + wid;        // warp-in-batch 0..15

    if (tid < 81) {
        const float t = trv[tid];
        tr_sh[tid] = t;
        Te_sm[tid / 9][tid % 9] = ex2f(t * L2E);
    }
    __syncthreads();

    // sequence length (mask is a prefix of ones)
    int len = 0;
    {
        const int* mrow = mask + (size_t)b * SS;
        for (int t = lane; t < SS; t += 32) len += mrow[t];
#pragma unroll
        for (int off = 16; off > 0; off >>= 1)
            len += __shfl_xor_sync(FULLMASK, len, off);
    }

    // ---- stage exp(emissions) for window [tb, tb+33), padded stride 12 ----
    const int tb = 1 + WIN * wb;
    {
        const float* base = g_emis + (size_t)b * SS * CC;
#pragma unroll 5
        for (int idx = lane; idx < WIN * CC; idx += 32) {
            const int row = idx / CC;
            const int cc  = idx - row * CC;
            const int tt  = tb + row;
            const int tc  = (tt < SS) ? tt : (SS - 1);   // clamp (unused if OOB)
            eml_sm[wid][row * 12 + cc] = ex2f(base[tc * CC + cc] * L2E);
        }
    }
    __syncwarp();

    // ---- numerator partial over [tb, tb+33) ----
    float np = 0.0f;
    for (int i = lane; i < WIN; i += 32) {
        const int t = tb + i;
        if (t < len) {
            const int tp = tags[(size_t)b * SS + t - 1];
            const int tc = tags[(size_t)b * SS + t];
            np += tr_sh[tp * CC + tc] + g_emis[((size_t)b * SS + t) * CC + tc];
        }
    }
#pragma unroll
    for (int off = 16; off > 0; off >>= 1)
        np += __shfl_xor_sync(FULLMASK, np, off);
    if (lane == 0) g_num[b * 16 + wb] = np;

    // ---- chunk matrix product: lane (s, r), chunk k = 3*wb + s ----
    const int ls = (lane < 27) ? lane : 26;
    const int s  = ls / 9;
    const int r  = ls - s * 9;

    float m[CC];
#pragma unroll
    for (int c = 0; c < CC; c++) m[c] = (c == r) ? 1.0f : 0.0f;
    int esum = 0;
    const int tbase = tb + s * CH;

#pragma unroll 1
    for (int i = 0; i < CH; i++) {
        if (tbase + i >= len) break;
        const float* emlrow = &eml_sm[wid][(s * CH + i) * 12];
        const float4 e0 = *(const float4*)&emlrow[0];
        const float4 e1 = *(const float4*)&emlrow[4];
        const float  e8 = emlrow[8];

        float v[CC];
#pragma unroll
        for (int c = 0; c < CC; c++) v[c] = 0.0f;
#pragma unroll
        for (int j = 0; j < CC; j++) {
            const float4 t0 = *(const float4*)&Te_sm[j][0];
            const float4 t1 = *(const float4*)&Te_sm[j][4];
            const float  t8 = Te_sm[j][8];
            const float  mj = m[j];
            v[0] = fmaf(mj, t0.x, v[0]); v[1] = fmaf(mj, t0.y, v[1]);
            v[2] = fmaf(mj, t0.z, v[2]); v[3] = fmaf(mj, t0.w, v[3]);
            v[4] = fmaf(mj, t1.x, v[4]); v[5] = fmaf(mj, t1.y, v[5]);
            v[6] = fmaf(mj, t1.z, v[6]); v[7] = fmaf(mj, t1.w, v[7]);
            v[8] = fmaf(mj, t8, v[8]);
        }
        v[0] *= e0.x; v[1] *= e0.y; v[2] *= e0.z; v[3] *= e0.w;
        v[4] *= e1.x; v[5] *= e1.y; v[6] *= e1.z; v[7] *= e1.w;
        v[8] *= e8;

        float mx01 = fmaxf(v[0], v[1]), mx23 = fmaxf(v[2], v[3]);
        float mx45 = fmaxf(v[4], v[5]), mx67 = fmaxf(v[6], v[7]);
        float mx = fmaxf(fmaxf(fmaxf(mx01, mx23), fmaxf(mx45, mx67)), v[8]);
        const int   eb  = (__float_as_int(mx) >> 23) & 0xff;
        const float pot = __int_as_float((254 - eb) << 23);
#pragma unroll
        for (int c = 0; c < CC; c++) m[c] = v[c] * pot;
        esum += eb - 127;
    }

    if (lane < 27) {
        const int k = 3 * wb + s;            // chunk id, start t = 1 + 11k
        float* dst = g_P + ((size_t)b * KCH + k) * 81 + r * 9;
#pragma unroll
        for (int c = 0; c < CC; c++) dst[c] = m[c];
        g_E[((size_t)b * KCH + k) * CC + r] = esum;
    }
    __syncthreads();

    // ---- arrival: second block for this batch does the combine ----
    if (tid == 0) {
        __threadfence();
        iam_last = (atomicAdd(&g_bar[b], 1) == 1);
    }
    __syncthreads();
    if (!iam_last) return;
    if (tid == 0) __threadfence();   // acquire the other half's writes
    __syncthreads();

    // ---- stage all 48 chunk matrices + exponents into smem ----
    for (int i = tid; i < KCH * 81 / 4 + 1; i += 256) {
        if (i < KCH * 81 / 4)
            ((float4*)Psm)[i] = ((const float4*)(g_P + (size_t)b * KCH * 81))[i];
    }
    Psm[KCH * 81 - 1] = g_P[(size_t)b * KCH * 81 + KCH * 81 - 1];  // 3888 = 972*4 exact
    for (int i = tid; i < KCH * CC; i += 256)
        Esm[i] = g_E[(size_t)b * KCH * CC + i];
    __syncthreads();

    // ---- per-chunk emax, in parallel (48 threads) ----
    if (tid < KCH) {
        int e = Esm[tid * CC];
#pragma unroll
        for (int r2 = 1; r2 < CC; r2++) e = max(e, Esm[tid * CC + r2]);
        Emax_sm[tid] = e;
    }
    __syncthreads();
    if (wid != 0) return;

    // ---- combine (warp 0): a unnormalized, true alpha = a * 2^E ----
    const int  c  = (lane < CC) ? lane : 0;
    const bool on = (lane < CC);
    float a = on ? ex2f((stv[c] + g_emis[(size_t)b * SS * CC + c]) * L2E) : 0.0f;
    int E = 0;

#pragma unroll 1
    for (int k = 0; k < KCH; k++) {
        if (1 + k * CH >= len) break;    // identity chunks beyond len

        const int emk = Emax_sm[k];                   // LDS broadcast
        const int ej  = on ? Esm[k * CC + lane] : emk;
        const int d   = ej - emk;                     // <= 0
        const float asc = (d > -126) ? a * __int_as_float((d + 127) << 23) : 0.0f;

        const float s0 = __shfl_sync(FULLMASK, asc, 0);
        const float s1 = __shfl_sync(FULLMASK, asc, 1);
        const float s2 = __shfl_sync(FULLMASK, asc, 2);
        const float s3 = __shfl_sync(FULLMASK, asc, 3);
        const float s4 = __shfl_sync(FULLMASK, asc, 4);
        const float s5 = __shfl_sync(FULLMASK, asc, 5);
        const float s6 = __shfl_sync(FULLMASK, asc, 6);
        const float s7 = __shfl_sync(FULLMASK, asc, 7);
        const float s8 = __shfl_sync(FULLMASK, asc, 8);

        // renorm scale from lane 0's exponent (s0 > 0 always)
        const int   e0 = (((__float_as_int(s0) >> 23) & 0xff)) - 127;
        const float sc = __int_as_float((127 - e0) << 23);   // 2^{-e0}

        const float* Pk = Psm + k * 81;
        float p0 = s0 * Pk[0 * 9 + c], p1 = s1 * Pk[1 * 9 + c];
        float p2 = s2 * Pk[2 * 9 + c], p3 = s3 * Pk[3 * 9 + c];
        float p4 = s4 * Pk[4 * 9 + c], p5 = s5 * Pk[5 * 9 + c];
        float p6 = s6 * Pk[6 * 9 + c], p7 = s7 * Pk[7 * 9 + c];
        float p8 = s8 * Pk[8 * 9 + c];
        float q0 = p0 + p1, q1 = p2 + p3, q2 = p4 + p5, q3 = p6 + p7;
        const float na = ((q0 + q1) + (q2 + q3)) + p8;

        a = on ? na * sc : 0.0f;
        E += emk + e0;
    }

    // ---- denominator ----
    float term = on ? a * ex2f(etv[c] * L2E) : 0.0f;
#pragma unroll
    for (int off = 16; off > 0; off >>= 1)
        term += __shfl_xor_sync(FULLMASK, term, off);
    const float denom = (lg2f(term) + (float)E) * LN2;

    // ---- numerator assembly ----
    float nsum = (lane < 16) ? g_num[b * 16 + lane] : 0.0f;
#pragma unroll
    for (int off = 16; off > 0; off >>= 1)
        nsum += __shfl_xor_sync(FULLMASK, nsum, off);
    const int first = tags[(size_t)b * SS];
    const int last  = tags[(size_t)b * SS + len - 1];
    const float num = nsum + stv[first]
                    + g_emis[(size_t)b * SS * CC + first] + etv[last];
    const float llh = num - denom;

    if (lane == 0) {
        g_bar[b] = 0;   // reset for next graph replay
        atomicAdd(&g_acc, llh);
        __threadfence();
        const int cnt = atomicAdd(&g_cnt, 1);
        if (cnt == BB - 1) {
            __threadfence();
            const float total = atomicAdd(&g_acc, 0.0f);
            out[0] = -total * (1.0f / (float)BB);
            g_acc = 0.0f;
            g_cnt = 0;
        }
    }
}

// ---------------------------------------------------------------------------
extern "C" void kernel_launch(void* const* d_in, const int* in_sizes, int n_in,
                              void* d_out, int out_size)
{
    (void)in_sizes; (void)n_in; (void)out_size;
    const float* hidden = (const float*)d_in[0];
    const float* W      = (const float*)d_in[1];
    const float* bias   = (const float*)d_in[2];
    const float* stv    = (const float*)d_in[3];
    const float* trv    = (const float*)d_in[4];
    const float* etv    = (const float*)d_in[5];
    const int*   tags   = (const int*)d_in[6];
    const int*   mask   = (const int*)d_in[7];

    emis_kernel<<<296, 256>>>(hidden, W, bias);
    crf_kernel<<<2 * BB, 256>>>(stv, trv, etv, tags, mask, (float*)d_out);
}

// round 14
// speedup vs baseline: 1.0370x; 1.0370x over previous
#include <cuda_runtime.h>
#include <cstdint>

#define BB 64
#define SS 512
#define HH 768
#define CC 9
#define KCH 48       // chunks per batch
#define CH  11       // steps per chunk (48*11 = 528 >= 511)
#define WPB 16       // warps per crf block
#define WIN 33       // timesteps per warp window (3 chunks * 11)
#define L2E 1.4426950408889634f
#define LN2 0.6931471805599453f
#define FULLMASK 0xffffffffu

// scratch (no allocations allowed)
__device__ __align__(16) float g_emis[BB * SS * CC];   // 1.18 MB raw emissions
__device__ float g_acc = 0.0f;
__device__ int   g_cnt = 0;

__device__ __forceinline__ float ex2f(float x) {
    float y; asm("ex2.approx.ftz.f32 %0, %1;" : "=f"(y) : "f"(x)); return y;
}
__device__ __forceinline__ float lg2f(float x) {
    float y; asm("lg2.approx.ftz.f32 %0, %1;" : "=f"(y) : "f"(x)); return y;
}

// ---------------------------------------------------------------------------
// Kernel 1: emissions = hidden @ W^T + b.
// 4 rows per warp, unroll 3 (12 LDG.128 in flight), vectorized STG.128 x9.
// ---------------------------------------------------------------------------
__global__ __launch_bounds__(256, 2) void emis_kernel(
    const float* __restrict__ hidden,
    const float* __restrict__ W,
    const float* __restrict__ bias)
{
    __shared__ alignas(16) float Wsm[CC * HH];   // 27648 B
    for (int i = threadIdx.x; i < CC * HH / 4; i += 256)
        ((float4*)Wsm)[i] = ((const float4*)W)[i];
    __syncthreads();

    float bv[CC];
#pragma unroll
    for (int c = 0; c < CC; c++) bv[c] = bias[c];

    const int lane   = threadIdx.x & 31;
    const int warp   = (blockIdx.x * blockDim.x + threadIdx.x) >> 5;
    const int nwarps = gridDim.x * (blockDim.x >> 5);
    const int NGROUPS = (BB * SS) / 4;   // 8192 groups of 4 rows

    for (int g = warp; g < NGROUPS; g += nwarps) {
        const int row0 = g * 4;
        const float4* hp0 = (const float4*)(hidden + (size_t)row0 * HH);
        const float4* hp1 = (const float4*)(hidden + (size_t)(row0 + 1) * HH);
        const float4* hp2 = (const float4*)(hidden + (size_t)(row0 + 2) * HH);
        const float4* hp3 = (const float4*)(hidden + (size_t)(row0 + 3) * HH);

        float acc[4][CC];
#pragma unroll
        for (int r = 0; r < 4; r++)
#pragma unroll
            for (int c = 0; c < CC; c++) acc[r][c] = 0.0f;

#pragma unroll 3
        for (int i = 0; i < HH / 128; i++) {   // 6 iterations
            float4 h[4];
            h[0] = hp0[i * 32 + lane];
            h[1] = hp1[i * 32 + lane];
            h[2] = hp2[i * 32 + lane];
            h[3] = hp3[i * 32 + lane];
#pragma unroll
            for (int c = 0; c < CC; c++) {
                const float4 w = ((const float4*)(Wsm + c * HH))[i * 32 + lane];
#pragma unroll
                for (int r = 0; r < 4; r++) {
                    acc[r][c] = fmaf(h[r].x, w.x, acc[r][c]);
                    acc[r][c] = fmaf(h[r].y, w.y, acc[r][c]);
                    acc[r][c] = fmaf(h[r].z, w.z, acc[r][c]);
                    acc[r][c] = fmaf(h[r].w, w.w, acc[r][c]);
                }
            }
        }
#pragma unroll
        for (int r = 0; r < 4; r++)
#pragma unroll
            for (int c = 0; c < CC; c++)
#pragma unroll
                for (int off = 16; off > 0; off >>= 1)
                    acc[r][c] += __shfl_xor_sync(FULLMASK, acc[r][c], off);

        if (lane == 0) {
            // 36 contiguous floats = 9 static float4 stores
#define AV(r, c) (acc[r][c] + bv[c])
            float4* dst = (float4*)(g_emis + (size_t)row0 * CC);
            dst[0] = make_float4(AV(0,0), AV(0,1), AV(0,2), AV(0,3));
            dst[1] = make_float4(AV(0,4), AV(0,5), AV(0,6), AV(0,7));
            dst[2] = make_float4(AV(0,8), AV(1,0), AV(1,1), AV(1,2));
            dst[3] = make_float4(AV(1,3), AV(1,4), AV(1,5), AV(1,6));
            dst[4] = make_float4(AV(1,7), AV(1,8), AV(2,0), AV(2,1));
            dst[5] = make_float4(AV(2,2), AV(2,3), AV(2,4), AV(2,5));
            dst[6] = make_float4(AV(2,6), AV(2,7), AV(2,8), AV(3,0));
            dst[7] = make_float4(AV(3,1), AV(3,2), AV(3,3), AV(3,4));
            dst[8] = make_float4(AV(3,5), AV(3,6), AV(3,7), AV(3,8));
#undef AV
        }
    }
}

// ---------------------------------------------------------------------------
// Kernel 2: full CRF per batch in ONE block (64 blocks x 512 threads).
// Phase 1: 16 warps, lane = (s, r); Te = exp(tr) held in 81 REGISTERS
//   (loaded once from smem) so the step loop has zero Te memory traffic.
//   Emissions pre-exponentiated at staging (padded stride 12, 3 LDS/step).
// Phase 2: warp 0 combines 48 chunks (early-exit past len), llh, atomic mean.
// ---------------------------------------------------------------------------
__global__ __launch_bounds__(512, 1) void crf_kernel(
    const float* __restrict__ stv,
    const float* __restrict__ trv,
    const float* __restrict__ etv,
    const int*   __restrict__ tags,
    const int*   __restrict__ mask,
    float* __restrict__ out)
{
    __shared__ alignas(16) float eml_sm[WPB][WIN * 12];  // 25344 B
    __shared__ alignas(16) float Psm[KCH * 81];          // 15552 B
    __shared__ alignas(16) float Te_lin[81];             // exp(tr), linear
    __shared__ int   Esm[KCH * CC];                      // 1728 B
    __shared__ float tr_sh[81];
    __shared__ float num_sm[WPB];
    __shared__ int   Emax_sm[KCH];

    const int b    = blockIdx.x;
    const int tid  = threadIdx.x;
    const int wid  = tid >> 5;
    const int lane = tid & 31;

    if (tid < 81) {
        const float t = trv[tid];
        tr_sh[tid] = t;
        Te_lin[tid] = ex2f(t * L2E);
    }
    __syncthreads();

    // Te into registers (one-time broadcast LDS; all indices compile-time)
    float Te[81];
#pragma unroll
    for (int j = 0; j < 81; j++) Te[j] = Te_lin[j];

    // sequence length (mask is a prefix of ones)
    int len = 0;
    {
        const int* mrow = mask + (size_t)b * SS;
        for (int t = lane; t < SS; t += 32) len += mrow[t];
#pragma unroll
        for (int off = 16; off > 0; off >>= 1)
            len += __shfl_xor_sync(FULLMASK, len, off);
    }

    // ---- stage exp(emissions) for window [tb, tb+33), padded stride 12 ----
    const int tb = 1 + WIN * wid;
    {
        const float* base = g_emis + (size_t)b * SS * CC;
#pragma unroll 5
        for (int idx = lane; idx < WIN * CC; idx += 32) {
            const int row = idx / CC;
            const int cc  = idx - row * CC;
            const int tt  = tb + row;
            const int tc  = (tt < SS) ? tt : (SS - 1);   // clamp (unused if OOB)
            eml_sm[wid][row * 12 + cc] = ex2f(base[tc * CC + cc] * L2E);
        }
    }
    __syncwarp();

    // ---- numerator partial over [tb, tb+33) ----
    float np = 0.0f;
    for (int i = lane; i < WIN; i += 32) {
        const int t = tb + i;
        if (t < len) {
            const int tp = tags[(size_t)b * SS + t - 1];
            const int tc = tags[(size_t)b * SS + t];
            np += tr_sh[tp * CC + tc] + g_emis[((size_t)b * SS + t) * CC + tc];
        }
    }
#pragma unroll
    for (int off = 16; off > 0; off >>= 1)
        np += __shfl_xor_sync(FULLMASK, np, off);
    if (lane == 0) num_sm[wid] = np;

    // ---- chunk matrix product: lane (s, r), chunk k = 3*wid + s ----
    const int ls = (lane < 27) ? lane : 26;
    const int s  = ls / 9;
    const int r  = ls - s * 9;

    float m[CC];
#pragma unroll
    for (int c = 0; c < CC; c++) m[c] = (c == r) ? 1.0f : 0.0f;
    int esum = 0;
    const int tbase = tb + s * CH;

#pragma unroll 1
    for (int i = 0; i < CH; i++) {
        if (tbase + i >= len) break;
        const float* emlrow = &eml_sm[wid][(s * CH + i) * 12];
        const float4 e0 = *(const float4*)&emlrow[0];
        const float4 e1 = *(const float4*)&emlrow[4];
        const float  e8 = emlrow[8];

        float v[CC];
#pragma unroll
        for (int c = 0; c < CC; c++) v[c] = 0.0f;
#pragma unroll
        for (int j = 0; j < CC; j++)
#pragma unroll
            for (int c = 0; c < CC; c++)
                v[c] = fmaf(m[j], Te[j * 9 + c], v[c]);

        v[0] *= e0.x; v[1] *= e0.y; v[2] *= e0.z; v[3] *= e0.w;
        v[4] *= e1.x; v[5] *= e1.y; v[6] *= e1.z; v[7] *= e1.w;
        v[8] *= e8;

        float mx01 = fmaxf(v[0], v[1]), mx23 = fmaxf(v[2], v[3]);
        float mx45 = fmaxf(v[4], v[5]), mx67 = fmaxf(v[6], v[7]);
        float mx = fmaxf(fmaxf(fmaxf(mx01, mx23), fmaxf(mx45, mx67)), v[8]);
        const int   eb  = (__float_as_int(mx) >> 23) & 0xff;
        const float pot = __int_as_float((254 - eb) << 23);
#pragma unroll
        for (int c = 0; c < CC; c++) m[c] = v[c] * pot;
        esum += eb - 127;
    }

    if (lane < 27) {
        const int k = 3 * wid + s;           // chunk id, start t = 1 + 11k
        float* dst = Psm + k * 81 + r * 9;
#pragma unroll
        for (int c = 0; c < CC; c++) dst[c] = m[c];
        Esm[k * CC + r] = esum;
    }
    __syncthreads();

    // ---- per-chunk emax, in parallel (48 threads) ----
    if (tid < KCH) {
        int e = Esm[tid * CC];
#pragma unroll
        for (int r2 = 1; r2 < CC; r2++) e = max(e, Esm[tid * CC + r2]);
        Emax_sm[tid] = e;
    }
    __syncthreads();
    if (wid != 0) return;

    // ---- combine (warp 0): a unnormalized, true alpha = a * 2^E ----
    const int  c  = (lane < CC) ? lane : 0;
    const bool on = (lane < CC);
    float a = on ? ex2f((stv[c] + g_emis[(size_t)b * SS * CC + c]) * L2E) : 0.0f;
    int E = 0;

#pragma unroll 1
    for (int k = 0; k < KCH; k++) {
        if (1 + k * CH >= len) break;    // identity chunks beyond len

        const int emk = Emax_sm[k];                   // LDS broadcast
        const int ej  = on ? Esm[k * CC + lane] : emk;
        const int d   = ej - emk;                     // <= 0
        const float asc = (d > -126) ? a * __int_as_float((d + 127) << 23) : 0.0f;

        const float s0 = __shfl_sync(FULLMASK, asc, 0);
        const float s1 = __shfl_sync(FULLMASK, asc, 1);
        const float s2 = __shfl_sync(FULLMASK, asc, 2);
        const float s3 = __shfl_sync(FULLMASK, asc, 3);
        const float s4 = __shfl_sync(FULLMASK, asc, 4);
        const float s5 = __shfl_sync(FULLMASK, asc, 5);
        const float s6 = __shfl_sync(FULLMASK, asc, 6);
        const float s7 = __shfl_sync(FULLMASK, asc, 7);
        const float s8 = __shfl_sync(FULLMASK, asc, 8);

        // renorm scale from lane 0's exponent (s0 > 0 always)
        const int   e0 = (((__float_as_int(s0) >> 23) & 0xff)) - 127;
        const float sc = __int_as_float((127 - e0) << 23);   // 2^{-e0}

        const float* Pk = Psm + k * 81;
        float p0 = s0 * Pk[0 * 9 + c], p1 = s1 * Pk[1 * 9 + c];
        float p2 = s2 * Pk[2 * 9 + c], p3 = s3 * Pk[3 * 9 + c];
        float p4 = s4 * Pk[4 * 9 + c], p5 = s5 * Pk[5 * 9 + c];
        float p6 = s6 * Pk[6 * 9 + c], p7 = s7 * Pk[7 * 9 + c];
        float p8 = s8 * Pk[8 * 9 + c];
        float q0 = p0 + p1, q1 = p2 + p3, q2 = p4 + p5, q3 = p6 + p7;
        const float na = ((q0 + q1) + (q2 + q3)) + p8;

        a = on ? na * sc : 0.0f;
        E += emk + e0;
    }

    // ---- denominator ----
    float term = on ? a * ex2f(etv[c] * L2E) : 0.0f;
#pragma unroll
    for (int off = 16; off > 0; off >>= 1)
        term += __shfl_xor_sync(FULLMASK, term, off);
    const float denom = (lg2f(term) + (float)E) * LN2;

    // ---- numerator assembly ----
    float nsum = (lane < WPB) ? num_sm[lane] : 0.0f;
#pragma unroll
    for (int off = 16; off > 0; off >>= 1)
        nsum += __shfl_xor_sync(FULLMASK, nsum, off);
    const int first = tags[(size_t)b * SS];
    const int last  = tags[(size_t)b * SS + len - 1];
    const float num = nsum + stv[first]
                    + g_emis[(size_t)b * SS * CC + first] + etv[last];
    const float llh = num - denom;

    if (lane == 0) {
        atomicAdd(&g_acc, llh);
        __threadfence();
        const int cnt = atomicAdd(&g_cnt, 1);
        if (cnt == BB - 1) {
            __threadfence();
            const float total = atomicAdd(&g_acc, 0.0f);
            out[0] = -total * (1.0f / (float)BB);
            g_acc = 0.0f;   // reset for next graph replay
            g_cnt = 0;
        }
    }
}

// ---------------------------------------------------------------------------
extern "C" void kernel_launch(void* const* d_in, const int* in_sizes, int n_in,
                              void* d_out, int out_size)
{
    (void)in_sizes; (void)n_in; (void)out_size;
    const float* hidden = (const float*)d_in[0];
    const float* W      = (const float*)d_in[1];
    const float* bias   = (const float*)d_in[2];
    const float* stv    = (const float*)d_in[3];
    const float* trv    = (const float*)d_in[4];
    const float* etv    = (const float*)d_in[5];
    const int*   tags   = (const int*)d_in[6];
    const int*   mask   = (const int*)d_in[7];

    emis_kernel<<<296, 256>>>(hidden, W, bias);
    crf_kernel<<<BB, 512>>>(stv, trv, etv, tags, mask, (float*)d_out);
}

// round 15
// speedup vs baseline: 1.0769x; 1.0384x over previous
#include <cuda_runtime.h>
#include <cstdint>

#define BB 64
#define SS 512
#define HH 768
#define CC 9
#define QB 4         // blocks per batch
#define BW 8         // warps per block
#define KCH 32       // chunks per batch (1 per warp)
#define CH 16        // steps per chunk (32*16 = 512 >= 511)
#define L2E 1.4426950408889634f
#define LN2 0.6931471805599453f
#define FULLMASK 0xffffffffu

// scratch (no allocations allowed)
__device__ __align__(16) float g_P[BB * KCH * 81];   // chunk matrices
__device__ int   g_E[BB * KCH * CC];                 // per-row exponents
__device__ float g_num[BB * KCH];                    // numerator partials
__device__ float g_emis0[BB * CC];                   // t=0 emissions
__device__ int   g_bar[BB];                          // per-batch arrivals
__device__ float g_acc = 0.0f;
__device__ int   g_cnt = 0;

__device__ __forceinline__ float ex2f(float x) {
    float y; asm("ex2.approx.ftz.f32 %0, %1;" : "=f"(y) : "f"(x)); return y;
}
__device__ __forceinline__ float lg2f(float x) {
    float y; asm("lg2.approx.ftz.f32 %0, %1;" : "=f"(y) : "f"(x)); return y;
}

// ---------------------------------------------------------------------------
// ONE kernel: grid (QB, BB) x 256. Block (q, b): 8 warps; warp w owns window
// k = q*8+w, timesteps [1+16k, 17+16k). Each warp: GEMV its 16 rows (proven
// 4-row groups) -> smem, exp -> smem, numerator partial, 16-step chunk matrix
// product -> gmem. Last block per batch combines (proven lean path) + mean.
// ---------------------------------------------------------------------------
__global__ __launch_bounds__(256, 2) void crf_fused_kernel(
    const float* __restrict__ hidden,
    const float* __restrict__ W,
    const float* __restrict__ bias,
    const float* __restrict__ stv,
    const float* __restrict__ trv,
    const float* __restrict__ etv,
    const int*   __restrict__ tags,
    const int*   __restrict__ mask,
    float* __restrict__ out)
{
    __shared__ alignas(16) float Wsm[CC * HH];        // 27648 B
    __shared__ alignas(16) union {
        struct {                                      // phase 1
            float raw[BW][CH * 12];                   // 6144 B raw emissions
            float eml[BW][CH * 12];                   // 6144 B exp(emissions)
        } p1;
        struct {                                      // phase 2 (combine blk)
            float P[KCH * 81];                        // 10368 B
            int   E[KCH * CC];                        // 1152 B
            int   Emax[KCH];                          // 128 B
        } p2;
    } u;
    __shared__ alignas(16) float Te_sm[CC][12];
    __shared__ float tr_sh[81];
    __shared__ float bias_sm[CC];
    __shared__ int   iam_last;

    const int q    = blockIdx.x;
    const int b    = blockIdx.y;
    const int tid  = threadIdx.x;
    const int wid  = tid >> 5;
    const int lane = tid & 31;
    const int k    = q * BW + wid;        // chunk/window id 0..31
    const int t0   = 1 + CH * k;          // first timestep of window

    for (int i = tid; i < CC * HH / 4; i += 256)
        ((float4*)Wsm)[i] = ((const float4*)W)[i];
    if (tid < 81) {
        const float t = trv[tid];
        tr_sh[tid] = t;
        Te_sm[tid / 9][tid % 9] = ex2f(t * L2E);
    }
    if (tid < CC) bias_sm[tid] = bias[tid];
    __syncthreads();

    // sequence length (mask is a prefix of ones)
    int len = 0;
    {
        const int* mrow = mask + (size_t)b * SS;
        for (int t = lane; t < SS; t += 32) len += mrow[t];
#pragma unroll
        for (int off = 16; off > 0; off >>= 1)
            len += __shfl_xor_sync(FULLMASK, len, off);
    }

    // ---- GEMV: 16 rows (+ t=0 extra group for q==0,wid==0) ----
    const int ngroups = (q == 0 && wid == 0) ? 5 : 4;
#pragma unroll 1
    for (int g = 0; g < ngroups; g++) {
        // groups 0..3: rows t0+4g+{0..3}; group 4 (special): rows {0,1,2,3}
        const int rbase = (g < 4) ? (t0 + 4 * g) : 0;
        const int r0 = (rbase + 0 < SS) ? rbase + 0 : SS - 1;
        const int r1 = (rbase + 1 < SS) ? rbase + 1 : SS - 1;
        const int r2 = (rbase + 2 < SS) ? rbase + 2 : SS - 1;
        const int r3 = (rbase + 3 < SS) ? rbase + 3 : SS - 1;
        const float4* hp0 = (const float4*)(hidden + ((size_t)b * SS + r0) * HH);
        const float4* hp1 = (const float4*)(hidden + ((size_t)b * SS + r1) * HH);
        const float4* hp2 = (const float4*)(hidden + ((size_t)b * SS + r2) * HH);
        const float4* hp3 = (const float4*)(hidden + ((size_t)b * SS + r3) * HH);

        float acc[4][CC];
#pragma unroll
        for (int r = 0; r < 4; r++)
#pragma unroll
            for (int c = 0; c < CC; c++) acc[r][c] = 0.0f;

#pragma unroll 3
        for (int i = 0; i < HH / 128; i++) {   // 6 iterations
            float4 h[4];
            h[0] = hp0[i * 32 + lane];
            h[1] = hp1[i * 32 + lane];
            h[2] = hp2[i * 32 + lane];
            h[3] = hp3[i * 32 + lane];
#pragma unroll
            for (int c = 0; c < CC; c++) {
                const float4 w = ((const float4*)(Wsm + c * HH))[i * 32 + lane];
#pragma unroll
                for (int r = 0; r < 4; r++) {
                    acc[r][c] = fmaf(h[r].x, w.x, acc[r][c]);
                    acc[r][c] = fmaf(h[r].y, w.y, acc[r][c]);
                    acc[r][c] = fmaf(h[r].z, w.z, acc[r][c]);
                    acc[r][c] = fmaf(h[r].w, w.w, acc[r][c]);
                }
            }
        }
#pragma unroll
        for (int r = 0; r < 4; r++)
#pragma unroll
            for (int c = 0; c < CC; c++)
#pragma unroll
                for (int off = 16; off > 0; off >>= 1)
                    acc[r][c] += __shfl_xor_sync(FULLMASK, acc[r][c], off);

        if (lane == 0) {
            if (g < 4) {
#pragma unroll
                for (int r = 0; r < 4; r++)
#pragma unroll
                    for (int c = 0; c < CC; c++)
                        u.p1.raw[wid][(4 * g + r) * 12 + c] = acc[r][c] + bias_sm[c];
            } else {
#pragma unroll
                for (int c = 0; c < CC; c++)
                    g_emis0[b * CC + c] = acc[0][c] + bias_sm[c];
            }
        }
    }
    __syncwarp();

    // ---- exponentiate emissions (spread across lanes) ----
    for (int idx = lane; idx < CH * CC; idx += 32) {
        const int row = idx / CC;
        const int cc  = idx - row * CC;
        u.p1.eml[wid][row * 12 + cc] = ex2f(u.p1.raw[wid][row * 12 + cc] * L2E);
    }
    __syncwarp();

    // ---- numerator partial over [t0, t0+16) ----
    float np = 0.0f;
    if (lane < CH) {
        const int t = t0 + lane;
        if (t < len) {
            const int tp = tags[(size_t)b * SS + t - 1];
            const int tc = tags[(size_t)b * SS + t];
            np = tr_sh[tp * CC + tc] + u.p1.raw[wid][lane * 12 + tc];
        }
    }
#pragma unroll
    for (int off = 16; off > 0; off >>= 1)
        np += __shfl_xor_sync(FULLMASK, np, off);
    if (lane == 0) g_num[b * KCH + k] = np;

    // ---- chunk matrix product: lane r < 9 holds row r of M ----
    const int r = (lane < CC) ? lane : 8;
    float m[CC];
#pragma unroll
    for (int c = 0; c < CC; c++) m[c] = (c == r) ? 1.0f : 0.0f;
    int esum = 0;

#pragma unroll 1
    for (int i = 0; i < CH; i++) {
        if (t0 + i >= len) break;
        const float* emlrow = &u.p1.eml[wid][i * 12];
        const float4 e0 = *(const float4*)&emlrow[0];
        const float4 e1 = *(const float4*)&emlrow[4];
        const float  e8 = emlrow[8];

        float v[CC];
#pragma unroll
        for (int c = 0; c < CC; c++) v[c] = 0.0f;
#pragma unroll
        for (int j = 0; j < CC; j++) {
            const float4 ta = *(const float4*)&Te_sm[j][0];
            const float4 tb2 = *(const float4*)&Te_sm[j][4];
            const float  t8 = Te_sm[j][8];
            const float  mj = m[j];
            v[0] = fmaf(mj, ta.x, v[0]); v[1] = fmaf(mj, ta.y, v[1]);
            v[2] = fmaf(mj, ta.z, v[2]); v[3] = fmaf(mj, ta.w, v[3]);
            v[4] = fmaf(mj, tb2.x, v[4]); v[5] = fmaf(mj, tb2.y, v[5]);
            v[6] = fmaf(mj, tb2.z, v[6]); v[7] = fmaf(mj, tb2.w, v[7]);
            v[8] = fmaf(mj, t8, v[8]);
        }
        v[0] *= e0.x; v[1] *= e0.y; v[2] *= e0.z; v[3] *= e0.w;
        v[4] *= e1.x; v[5] *= e1.y; v[6] *= e1.z; v[7] *= e1.w;
        v[8] *= e8;

        float mx01 = fmaxf(v[0], v[1]), mx23 = fmaxf(v[2], v[3]);
        float mx45 = fmaxf(v[4], v[5]), mx67 = fmaxf(v[6], v[7]);
        float mx = fmaxf(fmaxf(fmaxf(mx01, mx23), fmaxf(mx45, mx67)), v[8]);
        const int   eb  = (__float_as_int(mx) >> 23) & 0xff;
        const float pot = __int_as_float((254 - eb) << 23);
#pragma unroll
        for (int c = 0; c < CC; c++) m[c] = v[c] * pot;
        esum += eb - 127;
    }

    if (lane < CC) {
        float* dst = g_P + ((size_t)b * KCH + k) * 81 + r * 9;
#pragma unroll
        for (int c = 0; c < CC; c++) dst[c] = m[c];
        g_E[((size_t)b * KCH + k) * CC + r] = esum;
    }
    __syncthreads();

    // ---- arrival: last of the QB blocks for this batch combines ----
    if (tid == 0) {
        __threadfence();
        iam_last = (atomicAdd(&g_bar[b], 1) == QB - 1);
    }
    __syncthreads();
    if (!iam_last) return;
    if (tid == 0) __threadfence();   // acquire peers' writes
    __syncthreads();

    // ---- stage all 32 chunk matrices + exponents into smem ----
    for (int i = tid; i < KCH * 81 / 4; i += 256)
        ((float4*)u.p2.P)[i] = ((const float4*)(g_P + (size_t)b * KCH * 81))[i];
    for (int i = tid; i < KCH * CC; i += 256)
        u.p2.E[i] = g_E[(size_t)b * KCH * CC + i];
    __syncthreads();
    if (tid < KCH) {
        int e = u.p2.E[tid * CC];
#pragma unroll
        for (int r2 = 1; r2 < CC; r2++) e = max(e, u.p2.E[tid * CC + r2]);
        u.p2.Emax[tid] = e;
    }
    __syncthreads();
    if (wid != 0) return;

    // ---- combine (warp 0): a unnormalized, true alpha = a * 2^Etot ----
    const int  c  = (lane < CC) ? lane : 0;
    const bool on = (lane < CC);
    float a = on ? ex2f((stv[c] + g_emis0[b * CC + c]) * L2E) : 0.0f;
    int Etot = 0;

#pragma unroll 1
    for (int kk = 0; kk < KCH; kk++) {
        if (1 + kk * CH >= len) break;   // identity chunks beyond len

        const int emk = u.p2.Emax[kk];
        const int ej  = on ? u.p2.E[kk * CC + lane] : emk;
        const int d   = ej - emk;        // <= 0
        const float asc = (d > -126) ? a * __int_as_float((d + 127) << 23) : 0.0f;

        const float s0 = __shfl_sync(FULLMASK, asc, 0);
        const float s1 = __shfl_sync(FULLMASK, asc, 1);
        const float s2 = __shfl_sync(FULLMASK, asc, 2);
        const float s3 = __shfl_sync(FULLMASK, asc, 3);
        const float s4 = __shfl_sync(FULLMASK, asc, 4);
        const float s5 = __shfl_sync(FULLMASK, asc, 5);
        const float s6 = __shfl_sync(FULLMASK, asc, 6);
        const float s7 = __shfl_sync(FULLMASK, asc, 7);
        const float s8 = __shfl_sync(FULLMASK, asc, 8);

        const int   e0 = (((__float_as_int(s0) >> 23) & 0xff)) - 127;
        const float sc = __int_as_float((127 - e0) << 23);   // 2^{-e0}

        const float* Pk = u.p2.P + kk * 81;
        float p0 = s0 * Pk[0 * 9 + c], p1 = s1 * Pk[1 * 9 + c];
        float p2 = s2 * Pk[2 * 9 + c], p3 = s3 * Pk[3 * 9 + c];
        float p4 = s4 * Pk[4 * 9 + c], p5 = s5 * Pk[5 * 9 + c];
        float p6 = s6 * Pk[6 * 9 + c], p7 = s7 * Pk[7 * 9 + c];
        float p8 = s8 * Pk[8 * 9 + c];
        float q0 = p0 + p1, q1 = p2 + p3, q2 = p4 + p5, q3 = p6 + p7;
        const float na = ((q0 + q1) + (q2 + q3)) + p8;

        a = on ? na * sc : 0.0f;
        Etot += emk + e0;
    }

    // ---- denominator ----
    float term = on ? a * ex2f(etv[c] * L2E) : 0.0f;
#pragma unroll
    for (int off = 16; off > 0; off >>= 1)
        term += __shfl_xor_sync(FULLMASK, term, off);
    const float denom = (lg2f(term) + (float)Etot) * LN2;

    // ---- numerator assembly (32 partials = full warp) ----
    float nsum = g_num[b * KCH + lane];
#pragma unroll
    for (int off = 16; off > 0; off >>= 1)
        nsum += __shfl_xor_sync(FULLMASK, nsum, off);
    const int first = tags[(size_t)b * SS];
    const int last  = tags[(size_t)b * SS + len - 1];
    const float num = nsum + stv[first] + g_emis0[b * CC + first] + etv[last];
    const float llh = num - denom;

    if (lane == 0) {
        g_bar[b] = 0;   // reset for next graph replay
        atomicAdd(&g_acc, llh);
        __threadfence();
        const int cnt = atomicAdd(&g_cnt, 1);
        if (cnt == BB - 1) {
            __threadfence();
            const float total = atomicAdd(&g_acc, 0.0f);
            out[0] = -total * (1.0f / (float)BB);
            g_acc = 0.0f;
            g_cnt = 0;
        }
    }
}

// ---------------------------------------------------------------------------
extern "C" void kernel_launch(void* const* d_in, const int* in_sizes, int n_in,
                              void* d_out, int out_size)
{
    (void)in_sizes; (void)n_in; (void)out_size;
    const float* hidden = (const float*)d_in[0];
    const float* W      = (const float*)d_in[1];
    const float* bias   = (const float*)d_in[2];
    const float* stv    = (const float*)d_in[3];
    const float* trv    = (const float*)d_in[4];
    const float* etv    = (const float*)d_in[5];
    const int*   tags   = (const int*)d_in[6];
    const int*   mask   = (const int*)d_in[7];

    crf_fused_kernel<<<dim3(QB, BB), 256>>>(hidden, W, bias, stv, trv, etv,
                                            tags, mask, (float*)d_out);
}